// round 16
// baseline (speedup 1.0000x reference)
#include <cuda_runtime.h>

#define Bsz   128
#define Tt    512
#define INs   27
#define G4    1024
#define NB    128
#define OUTs  128

// ---- persistent device scratch (static: no runtime allocation) ----
__device__ float g_G[(size_t)Tt * G4 * Bsz];        // [t][g(1024)][b(128)]
// tagged-h ring: u64 = {h[2b+1] | h[2b]}, each fp32 carries step-tag in 2 LSBs.
// layout [slot(4)][grp(16)][k(256)][bpair(4)]
__device__ unsigned long long g_hx[4 * 16 * 256 * 4];

// ---------------- helpers ----------------
__device__ __forceinline__ void fma2(unsigned long long& d, unsigned long long a, unsigned long long b) {
    asm("fma.rn.f32x2 %0, %1, %2, %0;" : "+l"(d) : "l"(a), "l"(b));
}
__device__ __forceinline__ void add2(unsigned long long& d, unsigned long long a) {
    asm("add.rn.f32x2 %0, %0, %1;" : "+l"(d) : "l"(a));
}
__device__ __forceinline__ unsigned long long ldrx(const unsigned long long* p) {
    unsigned long long v;
    asm volatile("ld.relaxed.gpu.global.u64 %0, [%1];" : "=l"(v) : "l"(p) : "memory");
    return v;
}
__device__ __forceinline__ void strx(unsigned long long* p, unsigned long long v) {
    asm volatile("st.relaxed.gpu.global.u64 [%0], %1;" :: "l"(p), "l"(v) : "memory");
}
__device__ __forceinline__ float sigf(float x) {
    return __fdividef(1.f, 1.f + __expf(-x));
}
__device__ __forceinline__ float tanhf_(float x) {
    float e = __expf(-2.f * fabsf(x));
    float r = __fdividef(1.f - e, 1.f + e);
    return copysignf(r, x);
}

// ---------------- kernels ----------------
// G[t][g][b] = b_ih[g] + b_hh[g] + sum_{k<27} x[b][t][k] * W_ih[g][k]
// Also seed ring: slot 0 = h_0 = 0.0f (tag 0), slots 1..3 = tag-3 sentinel.
__global__ void pre_kernel(const float* __restrict__ x,
                           const float* __restrict__ W_ih,
                           const float* __restrict__ b_ih,
                           const float* __restrict__ b_hh) {
    __shared__ float xs[Bsz * INs];
    const int t   = blockIdx.x;
    const int gc  = blockIdx.y;       // 0..7, 128 gates each
    const int tid = threadIdx.x;      // = b  (blockDim.x == 128)

    if (gc == 0) {                    // 512*128 threads cover 65536 ring entries
        int e = t * 128 + tid;
        g_hx[e] = (e < 16384) ? 0ULL : 0x0000000300000003ULL;
    }

    for (int i = tid; i < Bsz * INs; i += 128) {
        int b = i / INs, k = i - b * INs;
        xs[i] = x[((size_t)b * Tt + t) * INs + k];
    }
    __syncthreads();
    float xr[INs];
    #pragma unroll
    for (int k = 0; k < INs; ++k) xr[k] = xs[tid * INs + k];

    for (int g0 = 0; g0 < 128; ++g0) {
        int g = (gc << 7) + g0;
        float acc = b_ih[g] + b_hh[g];
        const float* wr = W_ih + g * 47;   // NN_IN = 47, only first 27 cols used
        #pragma unroll
        for (int k = 0; k < INs; ++k) acc += xr[k] * __ldg(wr + k);
        g_G[((size_t)t * G4 + g) * Bsz + tid] = acc;
    }
}

// Persistent sequential LSTM, TWO chains per block (software pipelining).
// 128 blocks = 8 group-pairs x 16 j-tiles(16 j). Chains A = grp 2gp, B = 2gp+1
// share the same W registers. Warp = k-split ks(0..15, 16 k); lane = (gh, jl);
// thread = gates {2gh,2gh+1} of column j0+jl: w[2][16].
// Warps 0-1 run chain A's epilogue; warps 2-3 chain B's. Named barriers
// (A: ids 1/2 by parity, B: ids 3/4) decouple everyone else.
__global__ void __launch_bounds__(512, 1)
step_kernel(const float* __restrict__ W_hh,
            const float* __restrict__ W_fc,
            const float* __restrict__ b_fc,
            float* __restrict__ out) {
    extern __shared__ unsigned long long smu[];
    unsigned long long* sHdA = smu;               // 1024 u64
    unsigned long long* sHdB = smu + 1024;        // 1024 u64
    unsigned long long* sRA  = smu + 2048;        // 2 x 4096 u64 (parity)
    unsigned long long* sRB  = smu + 10240;       // 2 x 4096 u64 (parity)
    unsigned long long* sG   = smu + 18432;       // 512 u64: [tid(128)][q(4)]

    const int tid  = threadIdx.x;
    const int ks   = tid >> 5;                  // warp = k-split 0..15 (16 k)
    const int lane = tid & 31;
    const int jl   = lane & 15;                 // j-local 0..15
    const int gh   = lane >> 4;                 // gate-half 0..1
    const int gp   = blockIdx.x >> 4;           // group-pair 0..7
    const int jt   = blockIdx.x & 15;           // j-tile 0..15
    const int j0   = jt * 16;
    const int gA   = gp * 2, gB = gp * 2 + 1;
    const int bA0  = gA * 8, bB0 = gB * 8;

    // ---- W slice: 2 gate-rows x 16 k in registers, shared by both chains ----
    float w[2][16];
    #pragma unroll
    for (int qq = 0; qq < 2; ++qq) {
        const int q = gh * 2 + qq;
        const float* wp = W_hh + (q * 256 + j0 + jl) * 256 + ks * 16;
        #pragma unroll
        for (int kk = 0; kk < 16; ++kk) w[qq][kk] = wp[kk];
    }

    // epi roles: warps 0-1 -> chain A, warps 2-3 -> chain B
    const bool isEpiA = (ks < 2);
    const bool isEpiB = (ks == 2 || ks == 3);
    const int etid = tid & 63;                  // 0..63 within epi pair
    const int ej = etid & 15;                   // j-local
    const int eb = etid >> 4;                   // bpair 0..3
    unsigned sGa = 0;
    if (tid < 128) {
        unsigned sbase;
        asm("{ .reg .u64 t; cvta.to.shared.u64 t, %1; cvt.u32.u64 %0, t; }"
            : "=r"(sbase) : "l"(sG));
        sGa = sbase + tid * 32;                 // 4 u64 per epi thread
    }

    float c0 = 0.f, c1 = 0.f;                   // per-chain cell state (epi threads)

    for (int s = 0; s < Tt; ++s) {
        const size_t slotIn  = (size_t)(s & 3) * 16384;
        const size_t slotOut = (size_t)((s + 1) & 3) * 16384;
        const unsigned long long pat =
            (unsigned long long)((unsigned)(s >> 2) & 3u) * 0x0000000100000001ULL;
        const unsigned tagv = ((unsigned)(s + 1) >> 2) & 3u;

        // ---- issue G prefetch via cp.async (epi threads, own chain) ----
        if (tid < 128) {
            const int b0X = isEpiA ? bA0 : bB0;
            #pragma unroll
            for (int q = 0; q < 4; ++q) {
                const float* gs = g_G + ((size_t)s * 1024 + q * 256 + j0 + ej) * 128
                                      + b0X + eb * 2;
                asm volatile("cp.async.ca.shared.global [%0], [%1], 8;"
                             :: "r"(sGa + q * 8), "l"(gs) : "memory");
            }
            asm volatile("cp.async.commit_group;" ::: "memory");
        }

        // ================= chain A =================
        {   // poll + stage (warp-private region)
            const unsigned long long* p0 = g_hx + slotIn + (size_t)gA * 1024 + ks * 64 + lane;
            unsigned long long v0 = ldrx(p0), v1 = ldrx(p0 + 32);
            int spins = 0;
            while (((v0 & 0x0000000300000003ULL) != pat) ||
                   ((v1 & 0x0000000300000003ULL) != pat)) {
                if (++spins > 8) __nanosleep(40);
                if ((v0 & 0x0000000300000003ULL) != pat) v0 = ldrx(p0);
                if ((v1 & 0x0000000300000003ULL) != pat) v1 = ldrx(p0 + 32);
            }
            sHdA[ks * 64 + lane]      = v0;
            sHdA[ks * 64 + lane + 32] = v1;
        }
        __syncwarp();
        {   // GEMM A
            unsigned long long acc[2][4];
            #pragma unroll
            for (int qq = 0; qq < 2; ++qq)
                #pragma unroll
                for (int p = 0; p < 4; ++p) acc[qq][p] = 0ULL;
            #pragma unroll
            for (int kk = 0; kk < 16; ++kk) {
                const ulonglong2* hh = (const ulonglong2*)(sHdA + ks * 64 + kk * 4);
                ulonglong2 hA = hh[0], hB = hh[1];
                unsigned long long wd0, wd1;
                asm("mov.b64 %0, {%1, %1};" : "=l"(wd0) : "f"(w[0][kk]));
                asm("mov.b64 %0, {%1, %1};" : "=l"(wd1) : "f"(w[1][kk]));
                fma2(acc[0][0], hA.x, wd0); fma2(acc[0][1], hA.y, wd0);
                fma2(acc[0][2], hB.x, wd0); fma2(acc[0][3], hB.y, wd0);
                fma2(acc[1][0], hA.x, wd1); fma2(acc[1][1], hA.y, wd1);
                fma2(acc[1][2], hB.x, wd1); fma2(acc[1][3], hB.y, wd1);
            }
            unsigned long long* sRb = sRA + (s & 1) * 4096;
            #pragma unroll
            for (int qq = 0; qq < 2; ++qq)
                #pragma unroll
                for (int p = 0; p < 4; ++p)
                    sRb[ks * 256 + p * 64 + (gh * 2 + qq) * 16 + jl] = acc[qq][p];
        }
        {
            const int barA = 1 + (s & 1);
            if (isEpiA) {
                asm volatile("bar.sync %0, 512;" :: "r"(barA) : "memory");
                asm volatile("cp.async.wait_group 0;" ::: "memory");
                const unsigned long long* sRb = sRA + (s & 1) * 4096;
                unsigned long long vi = sG[tid * 4 + 0];
                unsigned long long vf = sG[tid * 4 + 1];
                unsigned long long vg = sG[tid * 4 + 2];
                unsigned long long vo = sG[tid * 4 + 3];
                const unsigned long long* rr = sRb + eb * 64 + ej;
                #pragma unroll
                for (int k2 = 0; k2 < 16; ++k2) {
                    add2(vi, rr[0]); add2(vf, rr[16]);
                    add2(vg, rr[32]); add2(vo, rr[48]);
                    rr += 256;
                }
                float iL, iH, fL, fH, gL, gH, oL, oH;
                asm("mov.b64 {%0, %1}, %2;" : "=f"(iL), "=f"(iH) : "l"(vi));
                asm("mov.b64 {%0, %1}, %2;" : "=f"(fL), "=f"(fH) : "l"(vf));
                asm("mov.b64 {%0, %1}, %2;" : "=f"(gL), "=f"(gH) : "l"(vg));
                asm("mov.b64 {%0, %1}, %2;" : "=f"(oL), "=f"(oH) : "l"(vo));
                c0 = sigf(fL) * c0 + sigf(iL) * tanhf_(gL);
                c1 = sigf(fH) * c1 + sigf(iH) * tanhf_(gH);
                float h0 = sigf(oL) * tanhf_(c0);
                float h1 = sigf(oH) * tanhf_(c1);
                unsigned u0 = (__float_as_uint(h0) & ~3u) | tagv;
                unsigned u1 = (__float_as_uint(h1) & ~3u) | tagv;
                strx(g_hx + slotOut + (size_t)gA * 1024 + (j0 + ej) * 4 + eb,
                     (unsigned long long)u0 | ((unsigned long long)u1 << 32));
            } else {
                asm volatile("bar.arrive %0, 512;" :: "r"(barA) : "memory");
            }
        }

        // ================= chain B =================
        {
            const unsigned long long* p0 = g_hx + slotIn + (size_t)gB * 1024 + ks * 64 + lane;
            unsigned long long v0 = ldrx(p0), v1 = ldrx(p0 + 32);
            int spins = 0;
            while (((v0 & 0x0000000300000003ULL) != pat) ||
                   ((v1 & 0x0000000300000003ULL) != pat)) {
                if (++spins > 8) __nanosleep(40);
                if ((v0 & 0x0000000300000003ULL) != pat) v0 = ldrx(p0);
                if ((v1 & 0x0000000300000003ULL) != pat) v1 = ldrx(p0 + 32);
            }
            sHdB[ks * 64 + lane]      = v0;
            sHdB[ks * 64 + lane + 32] = v1;
        }
        __syncwarp();
        {   // GEMM B
            unsigned long long acc[2][4];
            #pragma unroll
            for (int qq = 0; qq < 2; ++qq)
                #pragma unroll
                for (int p = 0; p < 4; ++p) acc[qq][p] = 0ULL;
            #pragma unroll
            for (int kk = 0; kk < 16; ++kk) {
                const ulonglong2* hh = (const ulonglong2*)(sHdB + ks * 64 + kk * 4);
                ulonglong2 hA = hh[0], hB = hh[1];
                unsigned long long wd0, wd1;
                asm("mov.b64 %0, {%1, %1};" : "=l"(wd0) : "f"(w[0][kk]));
                asm("mov.b64 %0, {%1, %1};" : "=l"(wd1) : "f"(w[1][kk]));
                fma2(acc[0][0], hA.x, wd0); fma2(acc[0][1], hA.y, wd0);
                fma2(acc[0][2], hB.x, wd0); fma2(acc[0][3], hB.y, wd0);
                fma2(acc[1][0], hA.x, wd1); fma2(acc[1][1], hA.y, wd1);
                fma2(acc[1][2], hB.x, wd1); fma2(acc[1][3], hB.y, wd1);
            }
            unsigned long long* sRb = sRB + (s & 1) * 4096;
            #pragma unroll
            for (int qq = 0; qq < 2; ++qq)
                #pragma unroll
                for (int p = 0; p < 4; ++p)
                    sRb[ks * 256 + p * 64 + (gh * 2 + qq) * 16 + jl] = acc[qq][p];
        }
        {
            const int barB = 3 + (s & 1);
            if (isEpiB) {
                asm volatile("bar.sync %0, 512;" :: "r"(barB) : "memory");
                asm volatile("cp.async.wait_group 0;" ::: "memory");
                const unsigned long long* sRb = sRB + (s & 1) * 4096;
                unsigned long long vi = sG[tid * 4 + 0];
                unsigned long long vf = sG[tid * 4 + 1];
                unsigned long long vg = sG[tid * 4 + 2];
                unsigned long long vo = sG[tid * 4 + 3];
                const unsigned long long* rr = sRb + eb * 64 + ej;
                #pragma unroll
                for (int k2 = 0; k2 < 16; ++k2) {
                    add2(vi, rr[0]); add2(vf, rr[16]);
                    add2(vg, rr[32]); add2(vo, rr[48]);
                    rr += 256;
                }
                float iL, iH, fL, fH, gL, gH, oL, oH;
                asm("mov.b64 {%0, %1}, %2;" : "=f"(iL), "=f"(iH) : "l"(vi));
                asm("mov.b64 {%0, %1}, %2;" : "=f"(fL), "=f"(fH) : "l"(vf));
                asm("mov.b64 {%0, %1}, %2;" : "=f"(gL), "=f"(gH) : "l"(vg));
                asm("mov.b64 {%0, %1}, %2;" : "=f"(oL), "=f"(oH) : "l"(vo));
                c0 = sigf(fL) * c0 + sigf(iL) * tanhf_(gL);
                c1 = sigf(fH) * c1 + sigf(iH) * tanhf_(gH);
                float h0 = sigf(oL) * tanhf_(c0);
                float h1 = sigf(oH) * tanhf_(c1);
                unsigned u0 = (__float_as_uint(h0) & ~3u) | tagv;
                unsigned u1 = (__float_as_uint(h1) & ~3u) | tagv;
                strx(g_hx + slotOut + (size_t)gB * 1024 + (j0 + ej) * 4 + eb,
                     (unsigned long long)u0 | ((unsigned long long)u1 << 32));
            } else {
                asm volatile("bar.arrive %0, 512;" :: "r"(barB) : "memory");
            }
        }
    }

    // ---- classifier head: batch bb = blockIdx.x; its group (bb>>3) is one of
    // this block's OWN chains (gp*2 + (jt>>3)) — self-synchronized, no aliasing.
    {
        float* sHf = (float*)smu;
        const int bb = blockIdx.x;
        if (tid < 256) {
            const unsigned long long* p =
                g_hx + (size_t)(bb >> 3) * 1024 + tid * 4 + ((bb & 7) >> 1);
            const unsigned sh = (bb & 1) * 32;
            unsigned long long v = ldrx(p);
            while ((unsigned)((v >> sh) & 3ULL) != 0u) { __nanosleep(40); v = ldrx(p); }
            sHf[tid] = __uint_as_float((unsigned)(v >> sh));
        }
        __syncthreads();
        if (tid < OUTs) {
            float acc = b_fc[tid];
            const float* wr = W_fc + tid * 256;
            #pragma unroll 8
            for (int k = 0; k < 256; ++k)
                acc += sHf[k] * wr[k];
            out[bb * OUTs + tid] = acc;
        }
    }
}

// ---------------- launcher ----------------
extern "C" void kernel_launch(void* const* d_in, const int* in_sizes, int n_in,
                              void* d_out, int out_size) {
    const float* x    = (const float*)d_in[0];
    // d_in[1] = input_lengths (unused by the reference)
    const float* W_ih = (const float*)d_in[2];
    const float* W_hh = (const float*)d_in[3];
    const float* b_ih = (const float*)d_in[4];
    const float* b_hh = (const float*)d_in[5];
    // d_in[6], d_in[7] = W_xi, b_xi — dead code (memory never affects output)
    const float* W_fc = (const float*)d_in[8];
    const float* b_fc = (const float*)d_in[9];
    float* out = (float*)d_out;

    // smem: 18944 u64 = 151552 bytes (sHd 16KB + sR 128KB + sG 4KB + pad)
    cudaFuncSetAttribute(step_kernel, cudaFuncAttributeMaxDynamicSharedMemorySize, 151552);

    pre_kernel<<<dim3(Tt, 8), 128>>>(x, W_ih, b_ih, b_hh);
    step_kernel<<<NB, 512, 151552>>>(W_hh, W_fc, b_fc, out);
}

// round 17
// speedup vs baseline: 1.0958x; 1.0958x over previous
#include <cuda_runtime.h>

#define Bsz   128
#define Tt    512
#define INs   27
#define G4    1024
#define NB    128
#define OUTs  128

// ---- persistent device scratch (static: no runtime allocation) ----
__device__ float g_G[(size_t)Tt * G4 * Bsz];        // [t][g(1024)][b(128)]
// tagged-h ring: u64 = {h[2b+1] | h[2b]}, each fp32 carries step-tag in 2 LSBs.
// layout [slot(4)][grp(16)][k(256)][bpair(4)]
__device__ unsigned long long g_hx[4 * 16 * 256 * 4];

// ---------------- helpers ----------------
__device__ __forceinline__ void fma2(unsigned long long& d, unsigned long long a, unsigned long long b) {
    asm("fma.rn.f32x2 %0, %1, %2, %0;" : "+l"(d) : "l"(a), "l"(b));
}
__device__ __forceinline__ void add2(unsigned long long& d, unsigned long long a) {
    asm("add.rn.f32x2 %0, %0, %1;" : "+l"(d) : "l"(a));
}
__device__ __forceinline__ unsigned long long ldrx(const unsigned long long* p) {
    unsigned long long v;
    asm volatile("ld.relaxed.gpu.global.u64 %0, [%1];" : "=l"(v) : "l"(p) : "memory");
    return v;
}
__device__ __forceinline__ void strx(unsigned long long* p, unsigned long long v) {
    asm volatile("st.relaxed.gpu.global.u64 [%0], %1;" :: "l"(p), "l"(v) : "memory");
}
__device__ __forceinline__ float sigf(float x) {
    return __fdividef(1.f, 1.f + __expf(-x));
}
__device__ __forceinline__ float tanhf_(float x) {
    float e = __expf(-2.f * fabsf(x));
    float r = __fdividef(1.f - e, 1.f + e);
    return copysignf(r, x);
}

// ---------------- kernels ----------------
// G[t][g][b] = b_ih[g] + b_hh[g] + sum_{k<27} x[b][t][k] * W_ih[g][k]
// Also seed ring: slot 0 = h_0 = 0.0f (tag 0), slots 1..3 = tag-3 sentinel.
__global__ void pre_kernel(const float* __restrict__ x,
                           const float* __restrict__ W_ih,
                           const float* __restrict__ b_ih,
                           const float* __restrict__ b_hh) {
    __shared__ float xs[Bsz * INs];
    const int t   = blockIdx.x;
    const int gc  = blockIdx.y;       // 0..7, 128 gates each
    const int tid = threadIdx.x;      // = b  (blockDim.x == 128)

    if (gc == 0) {                    // 512*128 threads cover 65536 ring entries
        int e = t * 128 + tid;
        g_hx[e] = (e < 16384) ? 0ULL : 0x0000000300000003ULL;
    }

    for (int i = tid; i < Bsz * INs; i += 128) {
        int b = i / INs, k = i - b * INs;
        xs[i] = x[((size_t)b * Tt + t) * INs + k];
    }
    __syncthreads();
    float xr[INs];
    #pragma unroll
    for (int k = 0; k < INs; ++k) xr[k] = xs[tid * INs + k];

    for (int g0 = 0; g0 < 128; ++g0) {
        int g = (gc << 7) + g0;
        float acc = b_ih[g] + b_hh[g];
        const float* wr = W_ih + g * 47;   // NN_IN = 47, only first 27 cols used
        #pragma unroll
        for (int k = 0; k < INs; ++k) acc += xr[k] * __ldg(wr + k);
        g_G[((size_t)t * G4 + g) * Bsz + tid] = acc;
    }
}

// Persistent sequential LSTM, TWO chains per block on DISJOINT WARPS.
// 128 blocks = 8 group-pairs x 16 j-tiles(16 j). Warps 0-7 = chain A (grp 2gp),
// warps 8-15 = chain B (grp 2gp+1). Within a chain: warp = k-split wk (32 k);
// thread = 2 gate-rows (row 2*lane, 2*lane+1 of the 64 = 4 gates x 16 j).
// HW warp scheduling overlaps chain A's poll/epilogue bubbles with chain B's GEMM.
// Per-chain parity-alternated named barriers (A: 1/2, B: 3/4), 256 threads each.
__global__ void __launch_bounds__(512, 1)
step_kernel(const float* __restrict__ W_hh,
            const float* __restrict__ W_fc,
            const float* __restrict__ b_fc,
            float* __restrict__ out) {
    extern __shared__ unsigned long long smu[];
    // [0,2048)      sHd:  chain*1024 + wk*128 + (klocal*4 + bp)
    // [2048,10240)  sR:   chain*4096 + parity*2048 + wk*256 + bp*64 + row(64)
    // [10240,10752) sG:   (chain*64 + etid)*4 + gate
    const int tid   = threadIdx.x;
    const int warp  = tid >> 5;
    const int lane  = tid & 31;
    const int chain = warp >> 3;                // 0 = A, 1 = B
    const int wk    = warp & 7;                 // k-split: k in [32wk, 32wk+32)
    const int gp    = blockIdx.x >> 4;          // group-pair 0..7
    const int jt    = blockIdx.x & 15;          // j-tile 0..15
    const int j0    = jt * 16;
    const int gX    = gp * 2 + chain;           // this warp's batch-group
    const int b0X   = gX * 8;

    // rows owned: r0 = 2*lane, r0+1 (same gate q, adjacent j)
    const int q   = lane >> 3;                  // gate 0..3
    const int jl0 = (lane & 7) * 2;             // j-local (even)

    // ---- W slice: 2 rows x 32 k in registers for the whole kernel ----
    float w0[32], w1[32];
    {
        const float* wp = W_hh + (q * 256 + j0 + jl0) * 256 + wk * 32;
        #pragma unroll
        for (int kk = 0; kk < 32; ++kk) { w0[kk] = wp[kk]; w1[kk] = wp[256 + kk]; }
    }

    unsigned long long* sHdX = smu + chain * 1024 + wk * 128;
    unsigned long long* sRX  = smu + 2048 + chain * 4096;
    unsigned long long* sG   = smu + 10240;

    // epilogue role: warps wk=0,1 of each chain; etid 0..63 -> (jl, bpair)
    const bool isEpi = (wk < 2);
    const int etid = wk * 32 + lane;
    const int jlE  = etid & 15;
    const int bpE  = etid >> 4;                 // 0..3
    unsigned sGa = 0;
    if (isEpi) {
        unsigned sbase;
        asm("{ .reg .u64 t; cvta.to.shared.u64 t, %1; cvt.u32.u64 %0, t; }"
            : "=r"(sbase) : "l"(sG));
        sGa = sbase + (unsigned)(chain * 64 + etid) * 32;
    }

    float c0 = 0.f, c1 = 0.f;                   // cell state (epi threads)

    for (int s = 0; s < Tt; ++s) {
        const size_t slotIn  = (size_t)(s & 3) * 16384;
        const size_t slotOut = (size_t)((s + 1) & 3) * 16384;
        const unsigned long long pat =
            (unsigned long long)((unsigned)(s >> 2) & 3u) * 0x0000000100000001ULL;
        const unsigned tagv = ((unsigned)(s + 1) >> 2) & 3u;

        // ---- G prefetch via cp.async (per-chain epi threads) ----
        if (isEpi) {
            #pragma unroll
            for (int qq = 0; qq < 4; ++qq) {
                const float* gs = g_G + ((size_t)s * 1024 + qq * 256 + j0 + jlE) * 128
                                      + b0X + bpE * 2;
                asm volatile("cp.async.ca.shared.global [%0], [%1], 8;"
                             :: "r"(sGa + qq * 8), "l"(gs) : "memory");
            }
            asm volatile("cp.async.commit_group;" ::: "memory");
        }

        // ---- poll own k-slice (4 u64/thread), warp-private staging ----
        {
            const unsigned long long* p0 =
                g_hx + slotIn + (size_t)gX * 1024 + wk * 128 + lane;
            unsigned long long v0 = ldrx(p0),      v1 = ldrx(p0 + 32);
            unsigned long long v2 = ldrx(p0 + 64), v3 = ldrx(p0 + 96);
            int spins = 0;
            while (((v0 & 0x0000000300000003ULL) != pat) ||
                   ((v1 & 0x0000000300000003ULL) != pat) ||
                   ((v2 & 0x0000000300000003ULL) != pat) ||
                   ((v3 & 0x0000000300000003ULL) != pat)) {
                if (++spins > 8) __nanosleep(40);
                if ((v0 & 0x0000000300000003ULL) != pat) v0 = ldrx(p0);
                if ((v1 & 0x0000000300000003ULL) != pat) v1 = ldrx(p0 + 32);
                if ((v2 & 0x0000000300000003ULL) != pat) v2 = ldrx(p0 + 64);
                if ((v3 & 0x0000000300000003ULL) != pat) v3 = ldrx(p0 + 96);
            }
            sHdX[lane]      = v0;
            sHdX[lane + 32] = v1;
            sHdX[lane + 64] = v2;
            sHdX[lane + 96] = v3;
        }
        __syncwarp();

        // ---- GEMM: 2 rows x 4 bpairs x 32 k; h broadcast LDS, W in regs ----
        unsigned long long a0[4], a1[4];
        #pragma unroll
        for (int p = 0; p < 4; ++p) { a0[p] = 0ULL; a1[p] = 0ULL; }

        #pragma unroll
        for (int kk = 0; kk < 32; ++kk) {
            const ulonglong2* hh = (const ulonglong2*)(sHdX + kk * 4);
            ulonglong2 hA = hh[0];              // bpairs 0,1 (broadcast)
            ulonglong2 hB = hh[1];              // bpairs 2,3
            unsigned long long wd0, wd1;
            asm("mov.b64 %0, {%1, %1};" : "=l"(wd0) : "f"(w0[kk]));
            asm("mov.b64 %0, {%1, %1};" : "=l"(wd1) : "f"(w1[kk]));
            fma2(a0[0], hA.x, wd0); fma2(a0[1], hA.y, wd0);
            fma2(a0[2], hB.x, wd0); fma2(a0[3], hB.y, wd0);
            fma2(a1[0], hA.x, wd1); fma2(a1[1], hA.y, wd1);
            fma2(a1[2], hB.x, wd1); fma2(a1[3], hB.y, wd1);
        }

        // ---- partials: sR[chain][buf][wk][bp][row], row pair as 16B store ----
        {
            unsigned long long* sRb = sRX + (s & 1) * 2048;
            #pragma unroll
            for (int p = 0; p < 4; ++p) {
                ulonglong2 pr; pr.x = a0[p]; pr.y = a1[p];
                *(ulonglong2*)(sRb + wk * 256 + p * 64 + 2 * lane) = pr;
            }
        }

        // ---- per-chain parity-alternated producer/consumer barrier ----
        const int barid = 1 + chain * 2 + (s & 1);
        if (!isEpi) {
            asm volatile("bar.arrive %0, 256;" :: "r"(barid) : "memory");
        } else {
            asm volatile("bar.sync %0, 256;" :: "r"(barid) : "memory");

            // ---- epilogue: sum 8 k-splits per gate, add G, LSTM, publish ----
            asm volatile("cp.async.wait_group 0;" ::: "memory");
            const unsigned long long* sRb = sRX + (s & 1) * 2048;
            const int gbase = (chain * 64 + etid) * 4;
            unsigned long long vi = sG[gbase + 0];
            unsigned long long vf = sG[gbase + 1];
            unsigned long long vg = sG[gbase + 2];
            unsigned long long vo = sG[gbase + 3];
            const unsigned long long* rr = sRb + bpE * 64 + jlE;
            #pragma unroll
            for (int k2 = 0; k2 < 8; ++k2) {
                add2(vi, rr[0]);
                add2(vf, rr[16]);
                add2(vg, rr[32]);
                add2(vo, rr[48]);
                rr += 256;
            }
            float iL, iH, fL, fH, gL, gH, oL, oH;
            asm("mov.b64 {%0, %1}, %2;" : "=f"(iL), "=f"(iH) : "l"(vi));
            asm("mov.b64 {%0, %1}, %2;" : "=f"(fL), "=f"(fH) : "l"(vf));
            asm("mov.b64 {%0, %1}, %2;" : "=f"(gL), "=f"(gH) : "l"(vg));
            asm("mov.b64 {%0, %1}, %2;" : "=f"(oL), "=f"(oH) : "l"(vo));
            c0 = sigf(fL) * c0 + sigf(iL) * tanhf_(gL);
            c1 = sigf(fH) * c1 + sigf(iH) * tanhf_(gH);
            float h0 = sigf(oL) * tanhf_(c0);
            float h1 = sigf(oH) * tanhf_(c1);
            unsigned u0 = (__float_as_uint(h0) & ~3u) | tagv;
            unsigned u1 = (__float_as_uint(h1) & ~3u) | tagv;
            strx(g_hx + slotOut + (size_t)gX * 1024 + (j0 + jlE) * 4 + bpE,
                 (unsigned long long)u0 | ((unsigned long long)u1 << 32));
        }
        // sR parity safety per chain: GEMM(s+2) stores gated by poll(h_{s+2})
        // -> this chain's epi(s+1) done -> epi(s) done. ✓
    }

    // ---- classifier head: batch bb = gp*16 + jt belongs to one of this block's
    // OWN chains (group bb>>3 = 2gp + (jt>>3)) — self-synchronized, no aliasing.
    {
        float* sHf = (float*)smu;
        const int bb = gp * 16 + jt;
        if (tid < 256) {
            const unsigned long long* p =
                g_hx + (size_t)(bb >> 3) * 1024 + tid * 4 + ((bb & 7) >> 1);
            const unsigned sh = (bb & 1) * 32;
            unsigned long long v = ldrx(p);
            while ((unsigned)((v >> sh) & 3ULL) != 0u) { __nanosleep(40); v = ldrx(p); }
            sHf[tid] = __uint_as_float((unsigned)(v >> sh));
        }
        __syncthreads();
        if (tid < OUTs) {
            float acc = b_fc[tid];
            const float* wr = W_fc + tid * 256;
            #pragma unroll 8
            for (int k = 0; k < 256; ++k)
                acc += sHf[k] * wr[k];
            out[bb * OUTs + tid] = acc;
        }
    }
}

// ---------------- launcher ----------------
extern "C" void kernel_launch(void* const* d_in, const int* in_sizes, int n_in,
                              void* d_out, int out_size) {
    const float* x    = (const float*)d_in[0];
    // d_in[1] = input_lengths (unused by the reference)
    const float* W_ih = (const float*)d_in[2];
    const float* W_hh = (const float*)d_in[3];
    const float* b_ih = (const float*)d_in[4];
    const float* b_hh = (const float*)d_in[5];
    // d_in[6], d_in[7] = W_xi, b_xi — dead code (memory never affects output)
    const float* W_fc = (const float*)d_in[8];
    const float* b_fc = (const float*)d_in[9];
    float* out = (float*)d_out;

    // smem: 10752 u64 = 86016 bytes
    cudaFuncSetAttribute(step_kernel, cudaFuncAttributeMaxDynamicSharedMemorySize, 86016);

    pre_kernel<<<dim3(Tt, 8), 128>>>(x, W_ih, b_ih, b_hh);
    step_kernel<<<NB, 512, 86016>>>(W_hh, W_fc, b_fc, out);
}